// round 8
// baseline (speedup 1.0000x reference)
#include <cuda_runtime.h>
#include <cuda_bf16.h>
#include <math.h>
#include <stdint.h>

#define TOKS   131072
#define CD     256
#define HIDD   1024
#define NHEAD  8
#define HD     32
#define NWIN   64

typedef __nv_bfloat16 bf16;

// ---------------- scratch ----------------------------------------------------
// g_xn, g_qkv, g_attn are WINDOW-MAJOR: row index = win*64 + n.
__device__ bf16  g_xn[(size_t)TOKS * CD];
__device__ bf16  g_qkv[(size_t)TOKS * 3 * CD];
__device__ bf16  g_attn[(size_t)TOKS * CD];
__device__ float g_x1[(size_t)TOKS * CD];          // token-major
__device__ bf16  g_x1n[(size_t)TOKS * CD];         // token-major
__device__ bf16  g_h[(size_t)TOKS * HIDD];         // token-major
__device__ bf16  g_wqkv[768 * 256];
__device__ bf16  g_wproj[256 * 256];
__device__ bf16  g_wfc1[1024 * 256];
__device__ bf16  g_wfc2[256 * 1024];
__device__ float g_bias[NHEAD * NWIN * NWIN];

// ---------------- helpers ----------------------------------------------------
__device__ __forceinline__ void ldsm4(uint32_t* r, uint32_t addr) {
    asm volatile("ldmatrix.sync.aligned.m8n8.x4.shared.b16 {%0,%1,%2,%3}, [%4];\n"
                 : "=r"(r[0]), "=r"(r[1]), "=r"(r[2]), "=r"(r[3]) : "r"(addr));
}
__device__ __forceinline__ void ldsm4t(uint32_t* r, uint32_t addr) {
    asm volatile("ldmatrix.sync.aligned.m8n8.x4.trans.shared.b16 {%0,%1,%2,%3}, [%4];\n"
                 : "=r"(r[0]), "=r"(r[1]), "=r"(r[2]), "=r"(r[3]) : "r"(addr));
}
__device__ __forceinline__ void mma16816(float* c, const uint32_t* a,
                                         uint32_t b0, uint32_t b1) {
    asm volatile("mma.sync.aligned.m16n8k16.row.col.f32.bf16.bf16.f32 "
                 "{%0,%1,%2,%3}, {%4,%5,%6,%7}, {%8,%9}, {%0,%1,%2,%3};\n"
                 : "+f"(c[0]), "+f"(c[1]), "+f"(c[2]), "+f"(c[3])
                 : "r"(a[0]), "r"(a[1]), "r"(a[2]), "r"(a[3]), "r"(b0), "r"(b1));
}
__device__ __forceinline__ void cpasync16(uint32_t dst, const void* src) {
    asm volatile("cp.async.cg.shared.global [%0], [%1], 16;\n" :: "r"(dst), "l"(src));
}
__device__ __forceinline__ uint32_t smaddr(const void* p) {
    return (uint32_t)__cvta_generic_to_shared(p);
}
__device__ __forceinline__ uint32_t sw128(uint32_t off) {
    return off ^ ((off >> 3) & 0x70);
}
__device__ __forceinline__ int token_of(int win, int n) {
    int b  = win >> 6;
    int wr = (win >> 3) & 7;
    int wc = win & 7;
    int r  = n >> 3;
    int c  = n & 7;
    return (b << 12) | (((wr << 3) + r) << 6) | ((wc << 3) + c);
}

// ---------------- prep -------------------------------------------------------
__global__ void prep_kernel(const float* __restrict__ wqkv, const float* __restrict__ wproj,
                            const float* __restrict__ wfc1, const float* __restrict__ wfc2,
                            const float* __restrict__ table) {
    int i = blockIdx.x * 256 + threadIdx.x;
    if (i < 196608) g_wqkv[i] = __float2bfloat16(wqkv[i]);
    if (i < 65536)  g_wproj[i] = __float2bfloat16(wproj[i]);
    if (i < 262144) g_wfc1[i] = __float2bfloat16(wfc1[i]);
    if (i < 262144) g_wfc2[i] = __float2bfloat16(wfc2[i]);
    if (i < 32768) {
        int h = i >> 12;
        int n = (i >> 6) & 63;
        int m = i & 63;
        int rid = ((n >> 3) - (m >> 3) + 7) * 15 + ((n & 7) - (m & 7) + 7);
        g_bias[i] = table[rid * NHEAD + h];
    }
}

// ---------------- LayerNorm --------------------------------------------------
template <int SRC>
__global__ void ln_kernel(const float* __restrict__ x, const float* __restrict__ g,
                          const float* __restrict__ b) {
    int row  = blockIdx.x * 8 + threadIdx.y;
    int lane = threadIdx.x;
    const float* xr = (SRC == 0 ? x : g_x1) + (size_t)row * CD;
    float v[8];
    float s = 0.f;
#pragma unroll
    for (int i = 0; i < 8; i++) { v[i] = xr[lane + 32 * i]; s += v[i]; }
#pragma unroll
    for (int o = 16; o; o >>= 1) s += __shfl_xor_sync(0xffffffffu, s, o);
    float mu = s * (1.f / 256.f);
    float q = 0.f;
#pragma unroll
    for (int i = 0; i < 8; i++) { float d = v[i] - mu; q += d * d; }
#pragma unroll
    for (int o = 16; o; o >>= 1) q += __shfl_xor_sync(0xffffffffu, q, o);
    float inv = rsqrtf(q * (1.f / 256.f) + 1e-5f);

    int orow;
    if (SRC == 0) {
        int bb  = row >> 12;
        int rem = row & 4095;
        int hr  = rem >> 6;
        int c   = rem & 63;
        int win = (bb << 6) | ((hr >> 3) << 3) | (c >> 3);
        int n   = ((hr & 7) << 3) | (c & 7);
        orow = (win << 6) | n;
    } else {
        orow = row;
    }
    bf16* po = (SRC == 0 ? g_xn : g_x1n) + (size_t)orow * CD;
#pragma unroll
    for (int i = 0; i < 8; i++) {
        int c = lane + 32 * i;
        po[c] = __float2bfloat16((v[i] - mu) * inv * g[c] + b[c]);
    }
}

// ---------------- GEMM: 3-stage cp.async, SW128 swizzle, 1 barrier/iter ------
// C[M,N] = A[M,K] @ W[N,K]^T. BM=BN=128, BK=64, 256 threads, 2 CTAs/SM.
// SMEM stage = A(16KB) + B(16KB) = 32KB; 3 stages = 96KB.
#define GS 3
#define GSTB 32768

template <int MODE>
__global__ void __launch_bounds__(256, 2) gemm_kernel(const float* __restrict__ bias,
                                                      const float* __restrict__ res,
                                                      float* __restrict__ outf) {
    constexpr int KD = (MODE == 3) ? 1024 : 256;
    constexpr int ND = (MODE == 0) ? 768 : (MODE == 2) ? 1024 : 256;
    const bf16* A = (MODE == 0) ? g_xn : (MODE == 1) ? g_attn : (MODE == 2) ? g_x1n : g_h;
    const bf16* W = (MODE == 0) ? g_wqkv : (MODE == 1) ? g_wproj : (MODE == 2) ? g_wfc1 : g_wfc2;

    extern __shared__ __align__(16) char sm[];
    uint32_t sb0 = smaddr(sm);

    int tid  = threadIdx.x;
    int lane = tid & 31;
    int wid  = tid >> 5;
    int wm   = wid & 3;
    int wn   = wid >> 2;
    int m0   = blockIdx.y * 128;
    int n0   = blockIdx.x * 128;

    float acc[2][8][4];
#pragma unroll
    for (int i = 0; i < 2; i++)
#pragma unroll
        for (int j = 0; j < 8; j++)
#pragma unroll
            for (int k = 0; k < 4; k++) acc[i][j][k] = 0.f;

    auto load_stage = [&](int it) {
        uint32_t sb = sb0 + (it % GS) * GSTB;
        int koff = it * 64;
#pragma unroll
        for (int t = 0; t < 8; t++) {
            int u   = tid + t * 256;            // 0..2047
            int row = u >> 3;                   // 0..255
            int cb  = (u & 7) << 4;             // byte col 0..112
            uint32_t off = (uint32_t)(row & 127) * 128 + cb;
            uint32_t dst = sb + ((row < 128) ? 0u : 16384u) + sw128(off);
            const char* src = (row < 128)
                ? (const char*)(A + (size_t)(m0 + row) * KD + koff) + cb
                : (const char*)(W + (size_t)(n0 + row - 128) * KD + koff) + cb;
            cpasync16(dst, src);
        }
        asm volatile("cp.async.commit_group;\n");
    };

    load_stage(0);
    load_stage(1);

    constexpr int NK = KD / 64;
    for (int it = 0; it < NK; it++) {
        if (it < NK - 1) {
            asm volatile("cp.async.wait_group 1;\n");
        } else {
            asm volatile("cp.async.wait_group 0;\n");
        }
        __syncthreads();
        if (it + 2 < NK) load_stage(it + 2);

        uint32_t sa = sb0 + (it % GS) * GSTB;
        uint32_t sbB = sa + 16384;
#pragma unroll
        for (int ks = 0; ks < 4; ks++) {
            uint32_t a[2][4], b[4][4];
#pragma unroll
            for (int mf = 0; mf < 2; mf++) {
                uint32_t off = (uint32_t)(wm * 32 + mf * 16 + (lane & 15)) * 128 +
                               ks * 32 + ((lane >> 4) << 4);
                ldsm4(a[mf], sa + sw128(off));
            }
#pragma unroll
            for (int np = 0; np < 4; np++) {
                uint32_t off = (uint32_t)(wn * 64 + np * 16 + ((lane >> 4) << 3) + (lane & 7)) * 128 +
                               ks * 32 + (((lane >> 3) & 1) << 4);
                ldsm4(b[np], sbB + sw128(off));
            }
#pragma unroll
            for (int mf = 0; mf < 2; mf++)
#pragma unroll
                for (int nf = 0; nf < 8; nf++)
                    mma16816(acc[mf][nf], a[mf], b[nf >> 1][(nf & 1) * 2],
                             b[nf >> 1][(nf & 1) * 2 + 1]);
        }
    }

    int er = lane >> 2;
    int ec = (lane & 3) << 1;
#pragma unroll
    for (int mf = 0; mf < 2; mf++) {
#pragma unroll
        for (int nf = 0; nf < 8; nf++) {
            int col = n0 + wn * 64 + nf * 8 + ec;
            float bx = bias[col], by = bias[col + 1];
#pragma unroll
            for (int half = 0; half < 2; half++) {
                int row = m0 + wm * 32 + mf * 16 + er + half * 8;
                float v0 = acc[mf][nf][half * 2] + bx;
                float v1 = acc[mf][nf][half * 2 + 1] + by;
                if (MODE == 0) {
                    size_t o = (size_t)row * ND + col;
                    *(__nv_bfloat162*)(g_qkv + o) = __floats2bfloat162_rn(v0, v1);
                } else if (MODE == 1) {
                    int trow = token_of(row >> 6, row & 63);
                    size_t o = (size_t)trow * ND + col;
                    float2 r2 = *(const float2*)&res[o];
                    g_x1[o]     = v0 + r2.x;
                    g_x1[o + 1] = v1 + r2.y;
                } else if (MODE == 2) {
                    size_t o = (size_t)row * ND + col;
                    float gx = 0.5f * v0 * (1.0f + erff(v0 * 0.70710678118654752f));
                    float gy = 0.5f * v1 * (1.0f + erff(v1 * 0.70710678118654752f));
                    *(__nv_bfloat162*)(g_h + o) = __floats2bfloat162_rn(gx, gy);
                } else {
                    size_t o = (size_t)row * ND + col;
                    float2 r2 = *(const float2*)&g_x1[o];
                    outf[o]     = v0 + r2.x;
                    outf[o + 1] = v1 + r2.y;
                }
            }
        }
    }
}

// ---------------- Attention: one block = (window, 4 heads) -------------------
__global__ void __launch_bounds__(256, 3) attn_kernel() {
    extern __shared__ __align__(16) bf16 smA[];
    bf16* Qs = smA;
    bf16* Ks = smA + 10240;
    bf16* Vs = smA + 20480;

    int win  = blockIdx.x;
    int hh   = blockIdx.y;
    int tid  = threadIdx.x;
    int lane = tid & 31;
    int wid  = tid >> 5;

    for (int u = tid; u < 3072; u += 256) {
        int tok = u / 48;
        int r   = u - tok * 48;
        int sec = r >> 4;
        int w   = r & 15;
        int h   = w >> 2;
        int dp  = (w & 3) << 3;
        uint4 val = *(const uint4*)(g_qkv + (size_t)((win << 6) + tok) * 768 +
                                    sec * 256 + ((hh << 2) + h) * 32 + dp);
        *(uint4*)(smA + sec * 10240 + (h * 64 + tok) * 40 + dp) = val;
    }
    __syncthreads();

    int h  = wid >> 1;
    int gh = (hh << 2) + h;
    int m0 = (wid & 1) << 5;
    const bf16* Qh = Qs + h * 2560;
    const bf16* Kh = Ks + h * 2560;
    const bf16* Vh = Vs + h * 2560;

    float s[2][8][4];
#pragma unroll
    for (int i = 0; i < 2; i++)
#pragma unroll
        for (int j = 0; j < 8; j++)
#pragma unroll
            for (int k = 0; k < 4; k++) s[i][j][k] = 0.f;

#pragma unroll
    for (int ks = 0; ks < 2; ks++) {
        uint32_t a[2][4];
#pragma unroll
        for (int mt = 0; mt < 2; mt++)
            ldsm4(a[mt], smaddr(&Qh[(m0 + mt * 16 + (lane & 15)) * 40 +
                                    ks * 16 + ((lane >> 4) << 3)]));
#pragma unroll
        for (int np = 0; np < 4; np++) {
            uint32_t b[4];
            ldsm4(b, smaddr(&Kh[(np * 16 + ((lane >> 4) << 3) + (lane & 7)) * 40 +
                                ks * 16 + (((lane >> 3) & 1) << 3)]));
#pragma unroll
            for (int mt = 0; mt < 2; mt++) {
                mma16816(s[mt][np * 2],     a[mt], b[0], b[1]);
                mma16816(s[mt][np * 2 + 1], a[mt], b[2], b[3]);
            }
        }
    }

    int q  = lane >> 2;
    int c2 = (lane & 3) << 1;
    const float* bh = g_bias + (gh << 12);
    const float scale = 0.17677669529663687f;
    uint32_t p[2][8][2];
#pragma unroll
    for (int mt = 0; mt < 2; mt++) {
#pragma unroll
        for (int hr = 0; hr < 2; hr++) {
            int gr = m0 + mt * 16 + hr * 8 + q;
            float v[16];
            float mx = -1e30f;
#pragma unroll
            for (int nt = 0; nt < 8; nt++) {
                float2 bb = *(const float2*)(bh + (gr << 6) + nt * 8 + c2);
                float v0 = fmaf(s[mt][nt][hr * 2],     scale, bb.x);
                float v1 = fmaf(s[mt][nt][hr * 2 + 1], scale, bb.y);
                v[nt * 2] = v0; v[nt * 2 + 1] = v1;
                mx = fmaxf(mx, fmaxf(v0, v1));
            }
            mx = fmaxf(mx, __shfl_xor_sync(0xffffffffu, mx, 1));
            mx = fmaxf(mx, __shfl_xor_sync(0xffffffffu, mx, 2));
            float sum = 0.f;
#pragma unroll
            for (int e = 0; e < 16; e++) { v[e] = __expf(v[e] - mx); sum += v[e]; }
            sum += __shfl_xor_sync(0xffffffffu, sum, 1);
            sum += __shfl_xor_sync(0xffffffffu, sum, 2);
            float inv = 1.f / sum;
#pragma unroll
            for (int nt = 0; nt < 8; nt++) {
                __nv_bfloat162 pk = __floats2bfloat162_rn(v[nt * 2] * inv, v[nt * 2 + 1] * inv);
                p[mt][nt][hr] = *(uint32_t*)&pk;
            }
        }
    }

    float o[2][4][4];
#pragma unroll
    for (int i = 0; i < 2; i++)
#pragma unroll
        for (int j = 0; j < 4; j++)
#pragma unroll
            for (int k = 0; k < 4; k++) o[i][j][k] = 0.f;

#pragma unroll
    for (int kt = 0; kt < 4; kt++) {
        uint32_t a0[4] = {p[0][2 * kt][0], p[0][2 * kt][1], p[0][2 * kt + 1][0], p[0][2 * kt + 1][1]};
        uint32_t a1[4] = {p[1][2 * kt][0], p[1][2 * kt][1], p[1][2 * kt + 1][0], p[1][2 * kt + 1][1]};
#pragma unroll
        for (int np = 0; np < 2; np++) {
            uint32_t b[4];
            ldsm4t(b, smaddr(&Vh[(kt * 16 + ((lane >> 3) & 1) * 8 + (lane & 7)) * 40 +
                                 np * 16 + ((lane >> 4) << 3)]));
            mma16816(o[0][np * 2],     a0, b[0], b[1]);
            mma16816(o[0][np * 2 + 1], a0, b[2], b[3]);
            mma16816(o[1][np * 2],     a1, b[0], b[1]);
            mma16816(o[1][np * 2 + 1], a1, b[2], b[3]);
        }
    }

#pragma unroll
    for (int mt = 0; mt < 2; mt++)
#pragma unroll
        for (int hr = 0; hr < 2; hr++) {
            int gr = m0 + mt * 16 + hr * 8 + q;
            size_t base = (size_t)((win << 6) + gr) * 256 + gh * 32;
#pragma unroll
            for (int nt = 0; nt < 4; nt++) {
                *(__nv_bfloat162*)(g_attn + base + nt * 8 + c2) =
                    __floats2bfloat162_rn(o[mt][nt][hr * 2], o[mt][nt][hr * 2 + 1]);
            }
        }
}

// ---------------- launch ------------------------------------------------------
extern "C" void kernel_launch(void* const* d_in, const int* in_sizes, int n_in,
                              void* d_out, int out_size) {
    const float* x     = (const float*)d_in[0];
    const float* g1    = (const float*)d_in[2];
    const float* b1    = (const float*)d_in[3];
    const float* wqkv  = (const float*)d_in[4];
    const float* bqkv  = (const float*)d_in[5];
    const float* table = (const float*)d_in[6];
    const float* wproj = (const float*)d_in[7];
    const float* bproj = (const float*)d_in[8];
    const float* g2    = (const float*)d_in[9];
    const float* b2    = (const float*)d_in[10];
    const float* wfc1  = (const float*)d_in[11];
    const float* bfc1  = (const float*)d_in[12];
    const float* wfc2  = (const float*)d_in[13];
    const float* bfc2  = (const float*)d_in[14];
    float* out = (float*)d_out;

    const int GEMM_SMEM = GS * GSTB;   // 98304
    cudaFuncSetAttribute(attn_kernel, cudaFuncAttributeMaxDynamicSharedMemorySize, 61440);
    cudaFuncSetAttribute(gemm_kernel<0>, cudaFuncAttributeMaxDynamicSharedMemorySize, GEMM_SMEM);
    cudaFuncSetAttribute(gemm_kernel<1>, cudaFuncAttributeMaxDynamicSharedMemorySize, GEMM_SMEM);
    cudaFuncSetAttribute(gemm_kernel<2>, cudaFuncAttributeMaxDynamicSharedMemorySize, GEMM_SMEM);
    cudaFuncSetAttribute(gemm_kernel<3>, cudaFuncAttributeMaxDynamicSharedMemorySize, GEMM_SMEM);

    prep_kernel<<<1024, 256>>>(wqkv, wproj, wfc1, wfc2, table);
    ln_kernel<0><<<TOKS / 8, dim3(32, 8)>>>(x, g1, b1);
    gemm_kernel<0><<<dim3(6, TOKS / 128), 256, GEMM_SMEM>>>(bqkv, nullptr, nullptr);
    attn_kernel<<<dim3(2048, 2), 256, 61440>>>();
    gemm_kernel<1><<<dim3(2, TOKS / 128), 256, GEMM_SMEM>>>(bproj, x, nullptr);
    ln_kernel<1><<<TOKS / 8, dim3(32, 8)>>>(nullptr, g2, b2);
    gemm_kernel<2><<<dim3(8, TOKS / 128), 256, GEMM_SMEM>>>(bfc1, nullptr, nullptr);
    gemm_kernel<3><<<dim3(2, TOKS / 128), 256, GEMM_SMEM>>>(bfc2, nullptr, out);
}

// round 11
// speedup vs baseline: 1.0470x; 1.0470x over previous
#include <cuda_runtime.h>
#include <cuda_bf16.h>
#include <math.h>
#include <stdint.h>

#define TOKS   131072
#define CD     256
#define HIDD   1024
#define NHEAD  8
#define HD     32
#define NWIN   64

typedef __nv_bfloat16 bf16;

// ---------------- scratch ----------------------------------------------------
// g_xn, g_qkv, g_attn are WINDOW-MAJOR: row index = win*64 + n.
__device__ bf16  g_xn[(size_t)TOKS * CD];
__device__ bf16  g_qkv[(size_t)TOKS * 3 * CD];
__device__ bf16  g_attn[(size_t)TOKS * CD];
__device__ float g_x1[(size_t)TOKS * CD];          // token-major
__device__ bf16  g_x1n[(size_t)TOKS * CD];         // token-major
__device__ bf16  g_h[(size_t)TOKS * HIDD];         // token-major
__device__ bf16  g_wqkv[768 * 256];
__device__ bf16  g_wproj[256 * 256];
__device__ bf16  g_wfc1[1024 * 256];
__device__ bf16  g_wfc2[256 * 1024];
__device__ float g_bias[NHEAD * NWIN * NWIN];

// ---------------- helpers ----------------------------------------------------
__device__ __forceinline__ void ldsm4(uint32_t* r, uint32_t addr) {
    asm volatile("ldmatrix.sync.aligned.m8n8.x4.shared.b16 {%0,%1,%2,%3}, [%4];\n"
                 : "=r"(r[0]), "=r"(r[1]), "=r"(r[2]), "=r"(r[3]) : "r"(addr));
}
__device__ __forceinline__ void ldsm4t(uint32_t* r, uint32_t addr) {
    asm volatile("ldmatrix.sync.aligned.m8n8.x4.trans.shared.b16 {%0,%1,%2,%3}, [%4];\n"
                 : "=r"(r[0]), "=r"(r[1]), "=r"(r[2]), "=r"(r[3]) : "r"(addr));
}
__device__ __forceinline__ void mma16816(float* c, const uint32_t* a,
                                         uint32_t b0, uint32_t b1) {
    asm volatile("mma.sync.aligned.m16n8k16.row.col.f32.bf16.bf16.f32 "
                 "{%0,%1,%2,%3}, {%4,%5,%6,%7}, {%8,%9}, {%0,%1,%2,%3};\n"
                 : "+f"(c[0]), "+f"(c[1]), "+f"(c[2]), "+f"(c[3])
                 : "r"(a[0]), "r"(a[1]), "r"(a[2]), "r"(a[3]), "r"(b0), "r"(b1));
}
__device__ __forceinline__ void cpasync16(void* dst, const void* src) {
    uint32_t d = (uint32_t)__cvta_generic_to_shared(dst);
    asm volatile("cp.async.cg.shared.global [%0], [%1], 16;\n" :: "r"(d), "l"(src));
}
__device__ __forceinline__ uint32_t smaddr(const void* p) {
    return (uint32_t)__cvta_generic_to_shared(p);
}
__device__ __forceinline__ uint32_t sw64(uint32_t off) {
    return off ^ ((off >> 3) & 0x30);
}
__device__ __forceinline__ int token_of(int win, int n) {
    int b  = win >> 6;
    int wr = (win >> 3) & 7;
    int wc = win & 7;
    int r  = n >> 3;
    int c  = n & 7;
    return (b << 12) | (((wr << 3) + r) << 6) | ((wc << 3) + c);
}

// ---------------- prep -------------------------------------------------------
__global__ void prep_kernel(const float* __restrict__ wqkv, const float* __restrict__ wproj,
                            const float* __restrict__ wfc1, const float* __restrict__ wfc2,
                            const float* __restrict__ table) {
    int i = blockIdx.x * 256 + threadIdx.x;
    if (i < 196608) g_wqkv[i] = __float2bfloat16(wqkv[i]);
    if (i < 65536)  g_wproj[i] = __float2bfloat16(wproj[i]);
    if (i < 262144) g_wfc1[i] = __float2bfloat16(wfc1[i]);
    if (i < 262144) g_wfc2[i] = __float2bfloat16(wfc2[i]);
    if (i < 32768) {
        int h = i >> 12;
        int n = (i >> 6) & 63;
        int m = i & 63;
        int rid = ((n >> 3) - (m >> 3) + 7) * 15 + ((n & 7) - (m & 7) + 7);
        g_bias[i] = table[rid * NHEAD + h];
    }
}

// ---------------- LayerNorm --------------------------------------------------
template <int SRC>
__global__ void ln_kernel(const float* __restrict__ x, const float* __restrict__ g,
                          const float* __restrict__ b) {
    int row  = blockIdx.x * 8 + threadIdx.y;
    int lane = threadIdx.x;
    const float* xr = (SRC == 0 ? x : g_x1) + (size_t)row * CD;
    float v[8];
    float s = 0.f;
#pragma unroll
    for (int i = 0; i < 8; i++) { v[i] = xr[lane + 32 * i]; s += v[i]; }
#pragma unroll
    for (int o = 16; o; o >>= 1) s += __shfl_xor_sync(0xffffffffu, s, o);
    float mu = s * (1.f / 256.f);
    float q = 0.f;
#pragma unroll
    for (int i = 0; i < 8; i++) { float d = v[i] - mu; q += d * d; }
#pragma unroll
    for (int o = 16; o; o >>= 1) q += __shfl_xor_sync(0xffffffffu, q, o);
    float inv = rsqrtf(q * (1.f / 256.f) + 1e-5f);

    int orow;
    if (SRC == 0) {
        int bb  = row >> 12;
        int rem = row & 4095;
        int hr  = rem >> 6;
        int c   = rem & 63;
        int win = (bb << 6) | ((hr >> 3) << 3) | (c >> 3);
        int n   = ((hr & 7) << 3) | (c & 7);
        orow = (win << 6) | n;
    } else {
        orow = row;
    }
    bf16* po = (SRC == 0 ? g_xn : g_x1n) + (size_t)orow * CD;
#pragma unroll
    for (int i = 0; i < 8; i++) {
        int c = lane + 32 * i;
        po[c] = __float2bfloat16((v[i] - mu) * inv * g[c] + b[c]);
    }
}

// ---------------- GEMM (R4-proven: 2-stage cp.async, padded smem) ------------
template <int MODE>
__global__ void __launch_bounds__(256, 2) gemm_kernel(const float* __restrict__ bias,
                                                      const float* __restrict__ res,
                                                      float* __restrict__ outf) {
    constexpr int KD = (MODE == 3) ? 1024 : 256;
    constexpr int ND = (MODE == 0) ? 768 : (MODE == 2) ? 1024 : 256;
    const bf16* A = (MODE == 0) ? g_xn : (MODE == 1) ? g_attn : (MODE == 2) ? g_x1n : g_h;
    const bf16* W = (MODE == 0) ? g_wqkv : (MODE == 1) ? g_wproj : (MODE == 2) ? g_wfc1 : g_wfc2;

    extern __shared__ __align__(16) bf16 smem[];   // As[2][128][72] | Bs[2][128][72]

    int tid  = threadIdx.x;
    int lane = tid & 31;
    int wid  = tid >> 5;
    int wm   = wid & 3;
    int wn   = wid >> 2;
    int m0   = blockIdx.y * 128;
    int n0   = blockIdx.x * 128;

    float acc[2][8][4];
#pragma unroll
    for (int i = 0; i < 2; i++)
#pragma unroll
        for (int j = 0; j < 8; j++)
#pragma unroll
            for (int k = 0; k < 4; k++) acc[i][j][k] = 0.f;

    int lr = tid >> 3;
    int lc = (tid & 7) << 3;

    auto load_tile = [&](int buf, int kt) {
        const bf16* Ag = A + (size_t)(m0 + lr) * KD + kt + lc;
        const bf16* Wg = W + (size_t)(n0 + lr) * KD + kt + lc;
        bf16* As = smem + buf * 9216;
        bf16* Bs = smem + 18432 + buf * 9216;
#pragma unroll
        for (int p = 0; p < 4; p++) {
            cpasync16(&As[(lr + 32 * p) * 72 + lc], Ag + (size_t)32 * p * KD);
            cpasync16(&Bs[(lr + 32 * p) * 72 + lc], Wg + (size_t)32 * p * KD);
        }
    };

    load_tile(0, 0);
    asm volatile("cp.async.commit_group;\n");

    constexpr int NK = KD / 64;
#pragma unroll
    for (int i = 0; i < NK; i++) {
        if (i + 1 < NK) {
            load_tile((i + 1) & 1, (i + 1) * 64);
            asm volatile("cp.async.commit_group;\n");
            asm volatile("cp.async.wait_group 1;\n");
        } else {
            asm volatile("cp.async.wait_group 0;\n");
        }
        __syncthreads();
        const bf16* As = smem + (i & 1) * 9216;
        const bf16* Bs = smem + 18432 + (i & 1) * 9216;
#pragma unroll
        for (int ks = 0; ks < 4; ks++) {
            uint32_t a[2][4], b[4][4];
#pragma unroll
            for (int mf = 0; mf < 2; mf++)
                ldsm4(a[mf], smaddr(&As[(wm * 32 + mf * 16 + (lane & 15)) * 72 +
                                        ks * 16 + ((lane >> 4) << 3)]));
#pragma unroll
            for (int np = 0; np < 4; np++)
                ldsm4(b[np], smaddr(&Bs[(wn * 64 + np * 16 + ((lane >> 4) << 3) + (lane & 7)) * 72 +
                                        ks * 16 + (((lane >> 3) & 1) << 3)]));
#pragma unroll
            for (int mf = 0; mf < 2; mf++)
#pragma unroll
                for (int nf = 0; nf < 8; nf++)
                    mma16816(acc[mf][nf], a[mf], b[nf >> 1][(nf & 1) * 2],
                             b[nf >> 1][(nf & 1) * 2 + 1]);
        }
        __syncthreads();
    }

    int er = lane >> 2;
    int ec = (lane & 3) << 1;
#pragma unroll
    for (int mf = 0; mf < 2; mf++) {
#pragma unroll
        for (int nf = 0; nf < 8; nf++) {
            int col = n0 + wn * 64 + nf * 8 + ec;
            float bx = bias[col], by = bias[col + 1];
#pragma unroll
            for (int half = 0; half < 2; half++) {
                int row = m0 + wm * 32 + mf * 16 + er + half * 8;
                float v0 = acc[mf][nf][half * 2] + bx;
                float v1 = acc[mf][nf][half * 2 + 1] + by;
                if (MODE == 0) {
                    size_t o = (size_t)row * ND + col;
                    *(__nv_bfloat162*)(g_qkv + o) = __floats2bfloat162_rn(v0, v1);
                } else if (MODE == 1) {
                    int trow = token_of(row >> 6, row & 63);
                    size_t o = (size_t)trow * ND + col;
                    float2 r2 = *(const float2*)&res[o];
                    g_x1[o]     = v0 + r2.x;
                    g_x1[o + 1] = v1 + r2.y;
                } else if (MODE == 2) {
                    size_t o = (size_t)row * ND + col;
                    float gx = 0.5f * v0 * (1.0f + erff(v0 * 0.70710678118654752f));
                    float gy = 0.5f * v1 * (1.0f + erff(v1 * 0.70710678118654752f));
                    *(__nv_bfloat162*)(g_h + o) = __floats2bfloat162_rn(gx, gy);
                } else {
                    size_t o = (size_t)row * ND + col;
                    float2 r2 = *(const float2*)&g_x1[o];
                    outf[o]     = v0 + r2.x;
                    outf[o + 1] = v1 + r2.y;
                }
            }
        }
    }
}

// ---------------- Attention: (window, 4 heads), 16 warps, 16-row warp tile ---
// 512 threads. warp wid: head = wid>>2, rows [ (wid&3)*16, +16 ).
// SMEM: Q/K/V [4][64][32] bf16, SW64 swizzle, zero padding: 3*16384 = 49152 B.
// 2 CTAs/SM -> 1024 threads (50% occ).
__global__ void __launch_bounds__(512, 2) attn_kernel() {
    extern __shared__ __align__(16) char smA[];
    uint32_t sQ = smaddr(smA);
    uint32_t sK = sQ + 16384;
    uint32_t sV = sQ + 32768;

    int win  = blockIdx.x;
    int hh   = blockIdx.y;          // 0 -> heads 0-3, 1 -> heads 4-7
    int tid  = threadIdx.x;
    int lane = tid & 31;
    int wid  = tid >> 5;

    // stage QKV: 3072 uint4, coalesced reads (g_qkv window-major)
#pragma unroll
    for (int it = 0; it < 6; it++) {
        int u   = tid + it * 512;
        int tok = u / 48;
        int r   = u - tok * 48;
        int sec = r >> 4;
        int w   = r & 15;
        int h   = w >> 2;
        int dp  = (w & 3) << 3;      // element offset 0,8,16,24
        uint4 val = *(const uint4*)(g_qkv + (size_t)((win << 6) + tok) * 768 +
                                    sec * 256 + ((hh << 2) + h) * 32 + dp);
        uint32_t dst = sQ + sec * 16384 + h * 4096 + sw64((uint32_t)tok * 64 + dp * 2);
        *(uint4*)(smA + (dst - sQ)) = val;
    }
    __syncthreads();

    int h  = wid >> 2;              // local head 0..3
    int gh = (hh << 2) + h;
    int m0 = (wid & 3) << 4;        // 16-row tile
    uint32_t Qh = sQ + h * 4096;
    uint32_t Kh = sK + h * 4096;
    uint32_t Vh = sV + h * 4096;

    // S = Q K^T  (16 rows x 64 cols)
    float s[8][4];
#pragma unroll
    for (int j = 0; j < 8; j++)
#pragma unroll
        for (int k = 0; k < 4; k++) s[j][k] = 0.f;

#pragma unroll
    for (int ks = 0; ks < 2; ks++) {
        uint32_t a[4];
        ldsm4(a, Qh + sw64((uint32_t)(m0 + (lane & 15)) * 64 + ks * 32 + ((lane >> 4) << 4)));
#pragma unroll
        for (int np = 0; np < 4; np++) {
            uint32_t b[4];
            ldsm4(b, Kh + sw64((uint32_t)(np * 16 + ((lane >> 4) << 3) + (lane & 7)) * 64 +
                               ks * 32 + (((lane >> 3) & 1) << 4)));
            mma16816(s[np * 2],     a, b[0], b[1]);
            mma16816(s[np * 2 + 1], a, b[2], b[3]);
        }
    }

    // softmax (quad-owned rows), scale + bias folded
    int q  = lane >> 2;
    int c2 = (lane & 3) << 1;
    const float* bh = g_bias + (gh << 12);
    const float scale = 0.17677669529663687f;
    uint32_t p[8][2];
#pragma unroll
    for (int hr = 0; hr < 2; hr++) {
        int gr = m0 + hr * 8 + q;
        float v[16];
        float mx = -1e30f;
#pragma unroll
        for (int nt = 0; nt < 8; nt++) {
            float2 bb = *(const float2*)(bh + (gr << 6) + nt * 8 + c2);
            float v0 = fmaf(s[nt][hr * 2],     scale, bb.x);
            float v1 = fmaf(s[nt][hr * 2 + 1], scale, bb.y);
            v[nt * 2] = v0; v[nt * 2 + 1] = v1;
            mx = fmaxf(mx, fmaxf(v0, v1));
        }
        mx = fmaxf(mx, __shfl_xor_sync(0xffffffffu, mx, 1));
        mx = fmaxf(mx, __shfl_xor_sync(0xffffffffu, mx, 2));
        float sum = 0.f;
#pragma unroll
        for (int e = 0; e < 16; e++) { v[e] = __expf(v[e] - mx); sum += v[e]; }
        sum += __shfl_xor_sync(0xffffffffu, sum, 1);
        sum += __shfl_xor_sync(0xffffffffu, sum, 2);
        float inv = 1.f / sum;
#pragma unroll
        for (int nt = 0; nt < 8; nt++) {
            __nv_bfloat162 pk = __floats2bfloat162_rn(v[nt * 2] * inv, v[nt * 2 + 1] * inv);
            p[nt][hr] = *(uint32_t*)&pk;
        }
    }

    // O = P V  (16 rows x 32 dims)
    float o[4][4];
#pragma unroll
    for (int j = 0; j < 4; j++)
#pragma unroll
        for (int k = 0; k < 4; k++) o[j][k] = 0.f;

#pragma unroll
    for (int kt = 0; kt < 4; kt++) {
        uint32_t a0[4] = {p[2 * kt][0], p[2 * kt][1], p[2 * kt + 1][0], p[2 * kt + 1][1]};
#pragma unroll
        for (int np = 0; np < 2; np++) {
            uint32_t b[4];
            ldsm4t(b, Vh + sw64((uint32_t)(kt * 16 + ((lane >> 3) & 1) * 8 + (lane & 7)) * 64 +
                                np * 32 + ((lane >> 4) << 4)));
            mma16816(o[np * 2],     a0, b[0], b[1]);
            mma16816(o[np * 2 + 1], a0, b[2], b[3]);
        }
    }

#pragma unroll
    for (int hr = 0; hr < 2; hr++) {
        int gr = m0 + hr * 8 + q;
        size_t base = (size_t)((win << 6) + gr) * 256 + gh * 32;   // window-major
#pragma unroll
        for (int nt = 0; nt < 4; nt++) {
            *(__nv_bfloat162*)(g_attn + base + nt * 8 + c2) =
                __floats2bfloat162_rn(o[nt][hr * 2], o[nt][hr * 2 + 1]);
        }
    }
}

// ---------------- launch ------------------------------------------------------
extern "C" void kernel_launch(void* const* d_in, const int* in_sizes, int n_in,
                              void* d_out, int out_size) {
    const float* x     = (const float*)d_in[0];
    const float* g1    = (const float*)d_in[2];
    const float* b1    = (const float*)d_in[3];
    const float* wqkv  = (const float*)d_in[4];
    const float* bqkv  = (const float*)d_in[5];
    const float* table = (const float*)d_in[6];
    const float* wproj = (const float*)d_in[7];
    const float* bproj = (const float*)d_in[8];
    const float* g2    = (const float*)d_in[9];
    const float* b2    = (const float*)d_in[10];
    const float* wfc1  = (const float*)d_in[11];
    const float* bfc1  = (const float*)d_in[12];
    const float* wfc2  = (const float*)d_in[13];
    const float* bfc2  = (const float*)d_in[14];
    float* out = (float*)d_out;

    cudaFuncSetAttribute(attn_kernel, cudaFuncAttributeMaxDynamicSharedMemorySize, 49152);
    cudaFuncSetAttribute(gemm_kernel<0>, cudaFuncAttributeMaxDynamicSharedMemorySize, 73728);
    cudaFuncSetAttribute(gemm_kernel<1>, cudaFuncAttributeMaxDynamicSharedMemorySize, 73728);
    cudaFuncSetAttribute(gemm_kernel<2>, cudaFuncAttributeMaxDynamicSharedMemorySize, 73728);
    cudaFuncSetAttribute(gemm_kernel<3>, cudaFuncAttributeMaxDynamicSharedMemorySize, 73728);

    prep_kernel<<<1024, 256>>>(wqkv, wproj, wfc1, wfc2, table);
    ln_kernel<0><<<TOKS / 8, dim3(32, 8)>>>(x, g1, b1);
    gemm_kernel<0><<<dim3(6, TOKS / 128), 256, 73728>>>(bqkv, nullptr, nullptr);
    attn_kernel<<<dim3(2048, 2), 512, 49152>>>();
    gemm_kernel<1><<<dim3(2, TOKS / 128), 256, 73728>>>(bproj, x, nullptr);
    ln_kernel<1><<<TOKS / 8, dim3(32, 8)>>>(nullptr, g2, b2);
    gemm_kernel<2><<<dim3(8, TOKS / 128), 256, 73728>>>(bfc1, nullptr, nullptr);
    gemm_kernel<3><<<dim3(2, TOKS / 128), 256, 73728>>>(bfc2, nullptr, out);
}